// round 12
// baseline (speedup 1.0000x reference)
#include <cuda_runtime.h>
#include <cuda_fp16.h>
#include <cstdint>

// ============================ problem constants ============================
#define Bn      8
#define Np      16384
#define MCc     2048
#define KNNk    32
#define EMBc    256
#define MT      4                 // m-tiles per group (M = 128 rows)
#define NGROUPS (Bn * MCc / MT)   // 4096
#define GRID    152
#define NT      512

// Strides in halfs, padded so ldmatrix/stmatrix 8-row sets are conflict-free
// (row byte-stride mod 128 == 16).
#define PKH  136                  // h2 and W3 k-stride (K=128)
#define PKW  72                   // h1 and W2 k-stride (K=64)
#define H2SZ 34816                // one h2 buffer: 128*136*2 B
#define H1SZ 18432                // one h1 buffer: 128*72*2 B

// SMEM byte offsets (16B aligned)
#define S_W3  0                              // [256][136] half: 69632 B
#define S_H2  69632                          // 2 x 34816 B
#define S_H1  139264                         // 2 x 18432 B
#define S_W2  176128                         // [128][72] half: 18432 B
#define S_B2  194560                         // 128 f32
#define S_W1  195072                         // 192 f32
#define S_B1  195840                         // 64 f32
#define SMEM_BYTES 196096

// ============================ PTX helpers ============================
__device__ __forceinline__ void mma16(float* d, const uint32_t* a,
                                      uint32_t b0, uint32_t b1) {
    asm volatile(
        "mma.sync.aligned.m16n8k16.row.col.f32.f16.f16.f32 "
        "{%0,%1,%2,%3}, {%4,%5,%6,%7}, {%8,%9}, {%0,%1,%2,%3};"
        : "+f"(d[0]), "+f"(d[1]), "+f"(d[2]), "+f"(d[3])
        : "r"(a[0]), "r"(a[1]), "r"(a[2]), "r"(a[3]), "r"(b0), "r"(b1));
}

__device__ __forceinline__ void ldsm4(uint32_t* r, uint32_t addr) {
    asm volatile(
        "ldmatrix.sync.aligned.m8n8.x4.shared.b16 {%0,%1,%2,%3}, [%4];"
        : "=r"(r[0]), "=r"(r[1]), "=r"(r[2]), "=r"(r[3]) : "r"(addr));
}

__device__ __forceinline__ void stsm4(uint32_t addr, uint32_t r0, uint32_t r1,
                                      uint32_t r2, uint32_t r3) {
    asm volatile(
        "stmatrix.sync.aligned.m8n8.x4.shared.b16 [%0], {%1,%2,%3,%4};"
        :: "r"(addr), "r"(r0), "r"(r1), "r"(r2), "r"(r3) : "memory");
}

__device__ __forceinline__ uint32_t smem_u32(const void* p) {
    uint32_t a;
    asm("{ .reg .u64 t; cvta.to.shared.u64 t, %1; cvt.u32.u64 %0, t; }"
        : "=r"(a) : "l"(p));
    return a;
}

__device__ __forceinline__ uint32_t packh2(float a, float b) {
    __half2 h = __floats2half2_rn(a, b);
    return *reinterpret_cast<uint32_t*>(&h);
}

__device__ __forceinline__ void quad_bar(int id) {
    asm volatile("bar.sync %0, %1;" :: "r"(id), "r"(128) : "memory");
}

// ============================ kernel ============================
__global__ __launch_bounds__(NT, 1)
void patch_embed_mma(const float* __restrict__ xyz,
                     const float* __restrict__ centers,
                     const int*   __restrict__ idx_knn,
                     const float* __restrict__ W1,
                     const float* __restrict__ b1,
                     const float* __restrict__ W2,
                     const float* __restrict__ b2,
                     const float* __restrict__ W3,
                     const float* __restrict__ b3,
                     float*       __restrict__ out)
{
    extern __shared__ __align__(16) char smem[];
    __half* sW3h = reinterpret_cast<__half*>(smem + S_W3);
    __half* sW2h = reinterpret_cast<__half*>(smem + S_W2);
    __half* sH1h = reinterpret_cast<__half*>(smem + S_H1);
    float*  sB2  = reinterpret_cast<float*>(smem + S_B2);
    float*  sW1v = reinterpret_cast<float*>(smem + S_W1);
    float*  sB1v = reinterpret_cast<float*>(smem + S_B1);

    const int tid  = threadIdx.x;
    const int lane = tid & 31;
    const int wid  = tid >> 5;
    const int gp   = lane >> 2;
    const int tg   = lane & 3;

    // quad pipelines: mtp = m-block (quad id), nq = n quarter within quad.
    const int mtp = wid >> 2;
    const int nq  = wid & 3;
    const int bar = mtp + 1;

    // ---- one-time staging: fp16 weights ------------------------------------
    for (int i = tid; i < 256 * 128; i += NT) {       // W3 [n=256][k=128]
        int n = i >> 7, k = i & 127;
        sW3h[n * PKH + k] = __float2half_rn(W3[i]);
    }
    for (int i = tid; i < 128 * 64; i += NT) {        // W2 [n=128][k=64]
        int n = i >> 6, k = i & 63;
        sW2h[n * PKW + k] = __float2half_rn(W2[i]);
    }
    if (tid < 192) sW1v[tid] = W1[tid];
    if (tid < 64)  sB1v[tid] = b1[tid];
    if (tid < 128) sB2[tid]  = b2[tid];
    __syncthreads();

    // ---- precomputed smem addresses (bytes) --------------------------------
    const uint32_t sH1_b = smem_u32(smem + S_H1);
    const uint32_t sH2_b = smem_u32(smem + S_H2);
    const uint32_t sW3_b = smem_u32(sW3h);
    const uint32_t sW2_b = smem_u32(sW2h);
    // A frags: rows mtp*32 + m*16 + (lane&15), k-half (lane>>4)*8 halfs
    uint32_t a1Addr[2], a2Addr[2];
    #pragma unroll
    for (int m = 0; m < 2; ++m) {
        const int r  = mtp*32 + m*16 + (lane & 15);
        const int kh = (lane >> 4) << 3;
        a1Addr[m] = sH1_b + ((r * PKW + kh) << 1);
        a2Addr[m] = sH2_b + ((r * PKH + kh) << 1);
    }
    // B (W3): n = nq*64 + p*16 + (lane&7) + ((lane>>4)<<3); k-half ((lane>>3)&1)*8
    uint32_t b3Addr[4];
    #pragma unroll
    for (int p = 0; p < 4; ++p)
        b3Addr[p] = sW3_b +
            (((nq*64 + p*16 + (lane & 7) + ((lane >> 4) << 3)) * PKH
              + (((lane >> 3) & 1) << 3)) << 1);
    // B (W2): n = nq*32 + p*16 + ...
    uint32_t b2Addr[2];
    #pragma unroll
    for (int p = 0; p < 2; ++p)
        b2Addr[p] = sW2_b +
            (((nq*32 + p*16 + (lane & 7) + ((lane >> 4) << 3)) * PKW
              + (((lane >> 3) & 1) << 3)) << 1);
    // stmatrix (h2 epi): instr (m, p) stores tiles nt=2p,2p+1 of m-tile m.
    uint32_t stAddr[2][2];
    #pragma unroll
    for (int m = 0; m < 2; ++m)
        #pragma unroll
        for (int p = 0; p < 2; ++p) {
            const int mat = lane >> 3, rin = lane & 7;
            const int r = mtp*32 + m*16 + (mat & 1)*8 + rin;
            const int c = nq*32 + p*16 + (mat >> 1)*8;
            stAddr[m][p] = sH2_b + ((r * PKH + c) << 1);
        }

    // ---- layer-1 row for this thread ---------------------------------------
    const int row = mtp * 32 + lane;          // quad-local row
    const int cb  = nq * 16;                  // 16-channel block

    // ---- prologue: L1(g0) -> h1 buf0; prefetch coords(g0+GRID) -------------
    float px, py, pz;
    {
        const int bm = blockIdx.x * MT + mtp;
        const int ii = __ldg(&idx_knn[bm * KNNk + lane]);
        const float* p = xyz + ((size_t)(bm >> 11) * Np + ii) * 3;
        px = p[0] - __ldg(&centers[bm * 3 + 0]);
        py = p[1] - __ldg(&centers[bm * 3 + 1]);
        pz = p[2] - __ldg(&centers[bm * 3 + 2]);

        uint32_t pk[8];
        #pragma unroll
        for (int j = 0; j < 8; ++j) {
            const int o0 = cb + 2*j;
            float v0 = sB1v[o0],     v1 = sB1v[o0 + 1];
            v0 = fmaf(sW1v[o0*3 + 0], px, v0);
            v1 = fmaf(sW1v[o0*3 + 3], px, v1);
            v0 = fmaf(sW1v[o0*3 + 1], py, v0);
            v1 = fmaf(sW1v[o0*3 + 4], py, v1);
            v0 = fmaf(sW1v[o0*3 + 2], pz, v0);
            v1 = fmaf(sW1v[o0*3 + 5], pz, v1);
            pk[j] = packh2(fmaxf(v0, 0.f), fmaxf(v1, 0.f));
        }
        uint32_t* h1r = reinterpret_cast<uint32_t*>(sH1h + row * PKW + cb);
        *reinterpret_cast<uint4*>(h1r)     = make_uint4(pk[0], pk[1], pk[2], pk[3]);
        *reinterpret_cast<uint4*>(h1r + 4) = make_uint4(pk[4], pk[5], pk[6], pk[7]);

        // prefetch coords of g0+GRID
        const int g1  = (blockIdx.x + GRID < NGROUPS) ? blockIdx.x + GRID
                                                      : blockIdx.x;
        const int nbm = g1 * MT + mtp;
        const int ni  = __ldg(&idx_knn[nbm * KNNk + lane]);
        const float* q = xyz + ((size_t)(nbm >> 11) * Np + ni) * 3;
        px = q[0] - __ldg(&centers[nbm * 3 + 0]);
        py = q[1] - __ldg(&centers[nbm * 3 + 1]);
        pz = q[2] - __ldg(&centers[nbm * 3 + 2]);
    }
    quad_bar(bar);   // h1 buf0 visible to the quad

    int it = 0;
    for (int g = blockIdx.x; g < NGROUPS; g += GRID, ++it) {
        const int s = it & 1;
        const uint32_t h1cur = s ? (uint32_t)H1SZ : 0u;   // group g's h1
        const uint32_t h1nxt = s ? 0u : (uint32_t)H1SZ;
        const uint32_t h2off = s ? (uint32_t)H2SZ : 0u;

        // ---- step 1: L1(g+GRID) -> h1[nxt] (coords already in px/py/pz) ----
        {
            uint32_t pk[8];
            #pragma unroll
            for (int j = 0; j < 8; ++j) {
                const int o0 = cb + 2*j;
                float v0 = sB1v[o0],     v1 = sB1v[o0 + 1];
                v0 = fmaf(sW1v[o0*3 + 0], px, v0);
                v1 = fmaf(sW1v[o0*3 + 3], px, v1);
                v0 = fmaf(sW1v[o0*3 + 1], py, v0);
                v1 = fmaf(sW1v[o0*3 + 4], py, v1);
                v0 = fmaf(sW1v[o0*3 + 2], pz, v0);
                v1 = fmaf(sW1v[o0*3 + 5], pz, v1);
                pk[j] = packh2(fmaxf(v0, 0.f), fmaxf(v1, 0.f));
            }
            uint32_t* h1r = reinterpret_cast<uint32_t*>(
                sH1h + (h1nxt >> 1) + row * PKW + cb);
            *reinterpret_cast<uint4*>(h1r)     = make_uint4(pk[0], pk[1], pk[2], pk[3]);
            *reinterpret_cast<uint4*>(h1r + 4) = make_uint4(pk[4], pk[5], pk[6], pk[7]);
        }

        // ---- step 1b: prefetch idx(g+2*GRID) (overlaps GEMM1) --------------
        const int g2   = (g + 2*GRID < NGROUPS) ? g + 2*GRID : g;
        const int nbm2 = g2 * MT + mtp;
        const int nii  = __ldg(&idx_knn[nbm2 * KNNk + lane]);

        // ---- step 2: GEMM1(g): D1 = h1[cur] * W2^T  (4 k16 steps) ----------
        float acc1[2][4][4];
        #pragma unroll
        for (int m = 0; m < 2; ++m)
            #pragma unroll
            for (int nt = 0; nt < 4; ++nt)
                #pragma unroll
                for (int j = 0; j < 4; ++j) acc1[m][nt][j] = 0.f;

        #pragma unroll
        for (int ks = 0; ks < 4; ++ks) {
            const uint32_t k4 = (uint32_t)ks << 5;
            uint32_t a0[4], a1[4];
            ldsm4(a0, a1Addr[0] + h1cur + k4);
            ldsm4(a1, a1Addr[1] + h1cur + k4);
            #pragma unroll
            for (int p = 0; p < 2; ++p) {
                uint32_t bf[4];
                ldsm4(bf, b2Addr[p] + k4);
                mma16(acc1[0][2*p],     a0, bf[0], bf[1]);
                mma16(acc1[1][2*p],     a1, bf[0], bf[1]);
                mma16(acc1[0][2*p + 1], a0, bf[2], bf[3]);
                mma16(acc1[1][2*p + 1], a1, bf[2], bf[3]);
            }
        }

        // ---- step 3: epi1: h2[s] = fp16(relu(D1 + b2)) via stmatrix --------
        #pragma unroll
        for (int m = 0; m < 2; ++m)
            #pragma unroll
            for (int p = 0; p < 2; ++p) {
                uint32_t rr[2][2];
                #pragma unroll
                for (int h = 0; h < 2; ++h) {
                    const int nt = 2*p + h;
                    const int c0 = nq*32 + nt*8 + 2*tg;
                    const float bb0 = sB2[c0], bb1 = sB2[c0 + 1];
                    rr[h][0] = packh2(fmaxf(acc1[m][nt][0] + bb0, 0.f),
                                      fmaxf(acc1[m][nt][1] + bb1, 0.f));
                    rr[h][1] = packh2(fmaxf(acc1[m][nt][2] + bb0, 0.f),
                                      fmaxf(acc1[m][nt][3] + bb1, 0.f));
                }
                stsm4(stAddr[m][p] + h2off, rr[0][0], rr[0][1], rr[1][0], rr[1][1]);
            }

        // ---- step 3b: prefetch coords(g+2*GRID) (overlaps GEMM2) -----------
        {
            const float* q = xyz + ((size_t)(nbm2 >> 11) * Np + nii) * 3;
            px = q[0] - __ldg(&centers[nbm2 * 3 + 0]);
            py = q[1] - __ldg(&centers[nbm2 * 3 + 1]);
            pz = q[2] - __ldg(&centers[nbm2 * 3 + 2]);
        }

        quad_bar(bar);   // the single per-iter barrier (fences h1 and h2)

        // ---- step 5: GEMM2(g): D2 = h2[s] * W3^T  (8 k16 steps) ------------
        {
            float acc2[2][8][4];
            #pragma unroll
            for (int m = 0; m < 2; ++m)
                #pragma unroll
                for (int nt = 0; nt < 8; ++nt)
                    #pragma unroll
                    for (int j = 0; j < 4; ++j) acc2[m][nt][j] = 0.f;

            #pragma unroll
            for (int ks = 0; ks < 8; ++ks) {
                const uint32_t k4 = (uint32_t)ks << 5;
                uint32_t a0[4], a1[4];
                ldsm4(a0, a2Addr[0] + h2off + k4);
                ldsm4(a1, a2Addr[1] + h2off + k4);
                #pragma unroll
                for (int p = 0; p < 4; ++p) {
                    uint32_t bf[4];
                    ldsm4(bf, b3Addr[p] + k4);
                    mma16(acc2[0][2*p],     a0, bf[0], bf[1]);
                    mma16(acc2[1][2*p],     a1, bf[0], bf[1]);
                    mma16(acc2[0][2*p + 1], a0, bf[2], bf[3]);
                    mma16(acc2[1][2*p + 1], a1, bf[2], bf[3]);
                }
            }

            // ---- max over 32 k-rows of this warp's m-block + b3 + store ----
            const int bm = g * MT + mtp;
            #pragma unroll
            for (int nt = 0; nt < 8; ++nt) {
                float m0 = fmaxf(fmaxf(acc2[0][nt][0], acc2[0][nt][2]),
                                 fmaxf(acc2[1][nt][0], acc2[1][nt][2]));
                float m1 = fmaxf(fmaxf(acc2[0][nt][1], acc2[0][nt][3]),
                                 fmaxf(acc2[1][nt][1], acc2[1][nt][3]));
                #pragma unroll
                for (int ss = 4; ss < 32; ss <<= 1) {
                    m0 = fmaxf(m0, __shfl_xor_sync(0xffffffffu, m0, ss));
                    m1 = fmaxf(m1, __shfl_xor_sync(0xffffffffu, m1, ss));
                }
                if (lane < 4) {
                    const int c = nq*64 + nt*8 + 2*tg;
                    float2 r2;
                    r2.x = m0 + __ldg(&b3[c]);
                    r2.y = m1 + __ldg(&b3[c + 1]);
                    *reinterpret_cast<float2*>(&out[(size_t)bm * EMBc + c]) = r2;
                }
            }
        }
        // no trailing barrier: every produce/consume pair on h1/h2 buffers is
        // separated by exactly one quad_bar instance (see header comment).
    }
}

// ============================ launch ============================
extern "C" void kernel_launch(void* const* d_in, const int* in_sizes, int n_in,
                              void* d_out, int out_size)
{
    // metadata order: xyz, centers, idx_knn, W1, b1, W2, b2, W3, b3
    const float* xyz     = (const float*)d_in[0];
    const float* centers = (const float*)d_in[1];
    const int*   idx_knn = (const int*)  d_in[2];
    const float* W1      = (const float*)d_in[3];
    const float* b1      = (const float*)d_in[4];
    const float* W2      = (const float*)d_in[5];
    const float* b2      = (const float*)d_in[6];
    const float* W3      = (const float*)d_in[7];
    const float* b3      = (const float*)d_in[8];
    float* out = (float*)d_out;

    // Idempotent attribute set (capture-safe, no allocation).
    cudaFuncSetAttribute(patch_embed_mma,
                         cudaFuncAttributeMaxDynamicSharedMemorySize,
                         SMEM_BYTES);

    patch_embed_mma<<<GRID, NT, SMEM_BYTES>>>(
        xyz, centers, idx_knn, W1, b1, W2, b2, W3, b3, out);
}

// round 13
// speedup vs baseline: 1.4344x; 1.4344x over previous
#include <cuda_runtime.h>
#include <cuda_fp16.h>
#include <cstdint>

// ============================ problem constants ============================
#define Bn      8
#define Np      16384
#define MCc     2048
#define KNNk    32
#define EMBc    256
#define MT      4                 // m-tiles per group (M = 128 rows)
#define NGROUPS (Bn * MCc / MT)   // 4096
#define GRID    152
#define NT      512

// Strides in halfs, padded so (PK mod 64) == 8 -> row byte-stride mod 128
// == 16 -> ldmatrix 8-row sets conflict-free.
#define PKH  136                  // h2 and W3 k-stride (K=128)
#define PKW  72                   // h1 and W2 k-stride (K=64)

// SMEM byte offsets (all 16B aligned)
#define S_W3  0                              // [256][136] half: 69632 B
#define S_H2  69632                          // [128][136] half: 34816 B
#define S_H1  104448                         // [128][72]  half: 18432 B
#define S_W2  122880                         // [128][72]  half: 18432 B
#define S_B2  141312                         // 128 f32
#define S_W1  141824                         // 192 f32
#define S_B1  142592                         // 64 f32
#define SMEM_BYTES 142848

// ============================ PTX helpers ============================
__device__ __forceinline__ void mma16(float* d, const uint32_t* a,
                                      uint32_t b0, uint32_t b1) {
    asm volatile(
        "mma.sync.aligned.m16n8k16.row.col.f32.f16.f16.f32 "
        "{%0,%1,%2,%3}, {%4,%5,%6,%7}, {%8,%9}, {%0,%1,%2,%3};"
        : "+f"(d[0]), "+f"(d[1]), "+f"(d[2]), "+f"(d[3])
        : "r"(a[0]), "r"(a[1]), "r"(a[2]), "r"(a[3]), "r"(b0), "r"(b1));
}

__device__ __forceinline__ void ldsm4(uint32_t* r, uint32_t addr) {
    asm volatile(
        "ldmatrix.sync.aligned.m8n8.x4.shared.b16 {%0,%1,%2,%3}, [%4];"
        : "=r"(r[0]), "=r"(r[1]), "=r"(r[2]), "=r"(r[3]) : "r"(addr));
}

__device__ __forceinline__ uint32_t smem_u32(const void* p) {
    uint32_t a;
    asm("{ .reg .u64 t; cvta.to.shared.u64 t, %1; cvt.u32.u64 %0, t; }"
        : "=r"(a) : "l"(p));
    return a;
}

__device__ __forceinline__ uint32_t packh2(float a, float b) {
    __half2 h = __floats2half2_rn(a, b);
    return *reinterpret_cast<uint32_t*>(&h);
}

// quad-local barrier: 4 warps sharing one m-block (128 threads)
__device__ __forceinline__ void quad_bar(int id) {
    asm volatile("bar.sync %0, %1;" :: "r"(id), "r"(128) : "memory");
}

// ============================ kernel ============================
__global__ __launch_bounds__(NT, 1)
void patch_embed_mma(const float* __restrict__ xyz,
                     const float* __restrict__ centers,
                     const int*   __restrict__ idx_knn,
                     const float* __restrict__ W1,
                     const float* __restrict__ b1,
                     const float* __restrict__ W2,
                     const float* __restrict__ b2,
                     const float* __restrict__ W3,
                     const float* __restrict__ b3,
                     float*       __restrict__ out)
{
    extern __shared__ __align__(16) char smem[];
    __half* sW3h = reinterpret_cast<__half*>(smem + S_W3);
    __half* sH2h = reinterpret_cast<__half*>(smem + S_H2);
    __half* sH1h = reinterpret_cast<__half*>(smem + S_H1);
    __half* sW2h = reinterpret_cast<__half*>(smem + S_W2);
    float*  sB2  = reinterpret_cast<float*>(smem + S_B2);
    float*  sW1v = reinterpret_cast<float*>(smem + S_W1);
    float*  sB1v = reinterpret_cast<float*>(smem + S_B1);

    const int tid  = threadIdx.x;
    const int lane = tid & 31;
    const int wid  = tid >> 5;
    const int gp   = lane >> 2;
    const int tg   = lane & 3;

    // quad pipelines: mtp = m-block (quad id), nq = n quarter within quad.
    const int mtp = wid >> 2;
    const int nq  = wid & 3;
    const int bar = mtp + 1;

    // ---- one-time staging: fp16 weights ------------------------------------
    for (int i = tid; i < 256 * 128; i += NT) {       // W3 [n=256][k=128]
        int n = i >> 7, k = i & 127;
        sW3h[n * PKH + k] = __float2half_rn(W3[i]);
    }
    for (int i = tid; i < 128 * 64; i += NT) {        // W2 [n=128][k=64]
        int n = i >> 6, k = i & 63;
        sW2h[n * PKW + k] = __float2half_rn(W2[i]);
    }
    if (tid < 192) sW1v[tid] = W1[tid];
    if (tid < 64)  sB1v[tid] = b1[tid];
    if (tid < 128) sB2[tid]  = b2[tid];
    __syncthreads();

    // ---- precomputed LDSM base addresses (bytes) ---------------------------
    const uint32_t sH1_b = smem_u32(sH1h);
    const uint32_t sH2_b = smem_u32(sH2h);
    const uint32_t sW3_b = smem_u32(sW3h);
    const uint32_t sW2_b = smem_u32(sW2h);
    // A frags: rows mtp*32 + m*16 + (lane&15), k-half (lane>>4)*8 halfs
    uint32_t a1Addr[2], a2Addr[2];
    #pragma unroll
    for (int m = 0; m < 2; ++m) {
        const int r = mtp*32 + m*16 + (lane & 15);
        const int kh = (lane >> 4) << 3;
        a1Addr[m] = sH1_b + ((r * PKW + kh) << 1);
        a2Addr[m] = sH2_b + ((r * PKH + kh) << 1);
    }
    // B (W3): n = nq*64 + p*16 + (lane&7) + ((lane>>4)<<3); k-half ((lane>>3)&1)*8
    uint32_t b3Addr[4];
    #pragma unroll
    for (int p = 0; p < 4; ++p)
        b3Addr[p] = sW3_b +
            (((nq*64 + p*16 + (lane & 7) + ((lane >> 4) << 3)) * PKH
              + (((lane >> 3) & 1) << 3)) << 1);

    // ---- hoisted W2 B-fragments (loop-invariant): 8 ldsm4 once, 32 regs ----
    uint32_t bW2[4][2][4];
    {
        uint32_t b2Addr[2];
        #pragma unroll
        for (int p = 0; p < 2; ++p)
            b2Addr[p] = sW2_b +
                (((nq*32 + p*16 + (lane & 7) + ((lane >> 4) << 3)) * PKW
                  + (((lane >> 3) & 1) << 3)) << 1);
        #pragma unroll
        for (int ks = 0; ks < 4; ++ks)
            #pragma unroll
            for (int p = 0; p < 2; ++p)
                ldsm4(bW2[ks][p], b2Addr[p] + ((uint32_t)ks << 5));
    }

    // ---- gather state: this thread's fixed row = mtp*32 + lane -------------
    const int row = mtp * 32 + lane;          // quad-local layer-1 row
    const int cb  = nq * 16;                  // 16-channel block

    float px, py, pz;
    {
        const int bm = blockIdx.x * MT + mtp;
        const int ii = __ldg(&idx_knn[bm * KNNk + lane]);
        const float* p = xyz + ((size_t)(bm >> 11) * Np + ii) * 3;
        px = p[0] - __ldg(&centers[bm * 3 + 0]);
        py = p[1] - __ldg(&centers[bm * 3 + 1]);
        pz = p[2] - __ldg(&centers[bm * 3 + 2]);
    }

    for (int g = blockIdx.x; g < NGROUPS; g += GRID) {
        const int bm0 = g * MT;
        const int gn  = (g + GRID < NGROUPS) ? (g + GRID) : g;

        // ---- layer 1: 3->64 relu (fp32 math, fp16 store) -> h1 -------------
        {
            uint32_t pk[8];
            #pragma unroll
            for (int j = 0; j < 8; ++j) {
                const int o0 = cb + 2*j;
                float v0 = sB1v[o0],     v1 = sB1v[o0 + 1];
                v0 = fmaf(sW1v[o0*3 + 0], px, v0);
                v1 = fmaf(sW1v[o0*3 + 3], px, v1);
                v0 = fmaf(sW1v[o0*3 + 1], py, v0);
                v1 = fmaf(sW1v[o0*3 + 4], py, v1);
                v0 = fmaf(sW1v[o0*3 + 2], pz, v0);
                v1 = fmaf(sW1v[o0*3 + 5], pz, v1);
                pk[j] = packh2(fmaxf(v0, 0.f), fmaxf(v1, 0.f));
            }
            uint32_t* h1r = reinterpret_cast<uint32_t*>(sH1h + row * PKW + cb);
            *reinterpret_cast<uint4*>(h1r)     = make_uint4(pk[0], pk[1], pk[2], pk[3]);
            *reinterpret_cast<uint4*>(h1r + 4) = make_uint4(pk[4], pk[5], pk[6], pk[7]);
        }
        // prefetch next group's knn index (overlaps GEMM1)
        const int nbm = gn * MT + mtp;
        const int nii = __ldg(&idx_knn[nbm * KNNk + lane]);

        quad_bar(bar);   // quad's h1 writes visible; prior GEMM2 reads done

        // ---- GEMM1: D1[m-block x 128] = h1 * W2^T  (4 k16 steps) -----------
        {
            float acc1[2][4][4];
            #pragma unroll
            for (int m = 0; m < 2; ++m)
                #pragma unroll
                for (int nt = 0; nt < 4; ++nt)
                    #pragma unroll
                    for (int j = 0; j < 4; ++j) acc1[m][nt][j] = 0.f;

            #pragma unroll
            for (int ks = 0; ks < 4; ++ks) {
                const uint32_t k4 = (uint32_t)ks << 5;   // 16 halfs = 32 B
                uint32_t a0[4], a1[4];
                ldsm4(a0, a1Addr[0] + k4);
                ldsm4(a1, a1Addr[1] + k4);
                #pragma unroll
                for (int p = 0; p < 2; ++p) {
                    mma16(acc1[0][2*p],     a0, bW2[ks][p][0], bW2[ks][p][1]);
                    mma16(acc1[1][2*p],     a1, bW2[ks][p][0], bW2[ks][p][1]);
                    mma16(acc1[0][2*p + 1], a0, bW2[ks][p][2], bW2[ks][p][3]);
                    mma16(acc1[1][2*p + 1], a1, bW2[ks][p][2], bW2[ks][p][3]);
                }
            }

            // ---- epilogue 1: h2 = fp16(relu(D1 + b2)) (separate buffer) ----
            #pragma unroll
            for (int m = 0; m < 2; ++m) {
                const int r0 = mtp*32 + m*16 + gp;
                #pragma unroll
                for (int nt = 0; nt < 4; ++nt) {
                    const int c0 = nq*32 + nt*8 + 2*tg;
                    const float bb0 = sB2[c0], bb1 = sB2[c0 + 1];
                    const uint32_t lo = packh2(fmaxf(acc1[m][nt][0] + bb0, 0.f),
                                               fmaxf(acc1[m][nt][1] + bb1, 0.f));
                    const uint32_t hi = packh2(fmaxf(acc1[m][nt][2] + bb0, 0.f),
                                               fmaxf(acc1[m][nt][3] + bb1, 0.f));
                    *reinterpret_cast<uint32_t*>(sH2h + r0 * PKH + c0)       = lo;
                    *reinterpret_cast<uint32_t*>(sH2h + (r0 + 8) * PKH + c0) = hi;
                }
            }
        }
        // prefetch next group's coords (overlaps GEMM2)
        {
            const float* p = xyz + ((size_t)(nbm >> 11) * Np + nii) * 3;
            px = p[0] - __ldg(&centers[nbm * 3 + 0]);
            py = p[1] - __ldg(&centers[nbm * 3 + 1]);
            pz = p[2] - __ldg(&centers[nbm * 3 + 2]);
        }

        quad_bar(bar);   // quad's h2 writes visible; h1 reads done

        // ---- GEMM2: D2[m-block x 256] = h2 * W3^T  (8 k16 steps) -----------
        {
            float acc2[2][8][4];
            #pragma unroll
            for (int m = 0; m < 2; ++m)
                #pragma unroll
                for (int nt = 0; nt < 8; ++nt)
                    #pragma unroll
                    for (int j = 0; j < 4; ++j) acc2[m][nt][j] = 0.f;

            #pragma unroll
            for (int ks = 0; ks < 8; ++ks) {
                const uint32_t k4 = (uint32_t)ks << 5;
                uint32_t a0[4], a1[4];
                ldsm4(a0, a2Addr[0] + k4);
                ldsm4(a1, a2Addr[1] + k4);
                #pragma unroll
                for (int p = 0; p < 4; ++p) {
                    uint32_t bf[4];
                    ldsm4(bf, b3Addr[p] + k4);
                    mma16(acc2[0][2*p],     a0, bf[0], bf[1]);
                    mma16(acc2[1][2*p],     a1, bf[0], bf[1]);
                    mma16(acc2[0][2*p + 1], a0, bf[2], bf[3]);
                    mma16(acc2[1][2*p + 1], a1, bf[2], bf[3]);
                }
            }

            // ---- max over 32 k-rows of this warp's m-block + b3 + store ----
            const int bm = bm0 + mtp;
            #pragma unroll
            for (int nt = 0; nt < 8; ++nt) {
                float m0 = fmaxf(fmaxf(acc2[0][nt][0], acc2[0][nt][2]),
                                 fmaxf(acc2[1][nt][0], acc2[1][nt][2]));
                float m1 = fmaxf(fmaxf(acc2[0][nt][1], acc2[0][nt][3]),
                                 fmaxf(acc2[1][nt][1], acc2[1][nt][3]));
                #pragma unroll
                for (int s = 4; s < 32; s <<= 1) {
                    m0 = fmaxf(m0, __shfl_xor_sync(0xffffffffu, m0, s));
                    m1 = fmaxf(m1, __shfl_xor_sync(0xffffffffu, m1, s));
                }
                if (lane < 4) {
                    const int c = nq*64 + nt*8 + 2*tg;
                    float2 r2;
                    r2.x = m0 + __ldg(&b3[c]);
                    r2.y = m1 + __ldg(&b3[c + 1]);
                    *reinterpret_cast<float2*>(&out[(size_t)bm * EMBc + c]) = r2;
                }
            }
        }
        // no barrier here: next layer-1 writes h1, whose quad readers are
        // fenced by the first quad_bar of the next iteration.
    }
}

// ============================ launch ============================
extern "C" void kernel_launch(void* const* d_in, const int* in_sizes, int n_in,
                              void* d_out, int out_size)
{
    // metadata order: xyz, centers, idx_knn, W1, b1, W2, b2, W3, b3
    const float* xyz     = (const float*)d_in[0];
    const float* centers = (const float*)d_in[1];
    const int*   idx_knn = (const int*)  d_in[2];
    const float* W1      = (const float*)d_in[3];
    const float* b1      = (const float*)d_in[4];
    const float* W2      = (const float*)d_in[5];
    const float* b2      = (const float*)d_in[6];
    const float* W3      = (const float*)d_in[7];
    const float* b3      = (const float*)d_in[8];
    float* out = (float*)d_out;

    // Idempotent attribute set (capture-safe, no allocation).
    cudaFuncSetAttribute(patch_embed_mma,
                         cudaFuncAttributeMaxDynamicSharedMemorySize,
                         SMEM_BYTES);

    patch_embed_mma<<<GRID, NT, SMEM_BYTES>>>(
        xyz, centers, idx_knn, W1, b1, W2, b2, W3, b3, out);
}

// round 14
// speedup vs baseline: 1.4392x; 1.0033x over previous
#include <cuda_runtime.h>
#include <cuda_fp16.h>
#include <cstdint>

// ============================ problem constants ============================
#define Bn      8
#define Np      16384
#define MCc     2048
#define KNNk    32
#define EMBc    256
#define MT      4                 // m-tiles per group (M = 128 rows)
#define NGROUPS (Bn * MCc / MT)   // 4096
#define GRID    152
#define NT      512

// Strides in halfs, padded so (PK mod 64) == 8 -> row byte-stride mod 128
// == 16 -> ldmatrix/stmatrix 8-row sets conflict-free.
#define PKH  136                  // h2 and W3 k-stride (K=128)
#define PKW  72                   // h1 and W2 k-stride (K=64)

// SMEM byte offsets (all 16B aligned)
#define S_W3  0                              // [256][136] half: 69632 B
#define S_H2  69632                          // [128][136] half: 34816 B
#define S_H1  104448                         // [128][72]  half: 18432 B
#define S_W2  122880                         // [128][72]  half: 18432 B
#define S_B2  141312                         // 128 f32
#define S_W1  141824                         // 192 f32
#define S_B1  142592                         // 64 f32
#define SMEM_BYTES 142848

// ============================ PTX helpers ============================
__device__ __forceinline__ void mma16(float* d, const uint32_t* a,
                                      uint32_t b0, uint32_t b1) {
    asm volatile(
        "mma.sync.aligned.m16n8k16.row.col.f32.f16.f16.f32 "
        "{%0,%1,%2,%3}, {%4,%5,%6,%7}, {%8,%9}, {%0,%1,%2,%3};"
        : "+f"(d[0]), "+f"(d[1]), "+f"(d[2]), "+f"(d[3])
        : "r"(a[0]), "r"(a[1]), "r"(a[2]), "r"(a[3]), "r"(b0), "r"(b1));
}

__device__ __forceinline__ void ldsm4(uint32_t* r, uint32_t addr) {
    asm volatile(
        "ldmatrix.sync.aligned.m8n8.x4.shared.b16 {%0,%1,%2,%3}, [%4];"
        : "=r"(r[0]), "=r"(r[1]), "=r"(r[2]), "=r"(r[3]) : "r"(addr));
}

__device__ __forceinline__ void stsm4(uint32_t addr, uint32_t r0, uint32_t r1,
                                      uint32_t r2, uint32_t r3) {
    asm volatile(
        "stmatrix.sync.aligned.m8n8.x4.shared.b16 [%0], {%1,%2,%3,%4};"
        :: "r"(addr), "r"(r0), "r"(r1), "r"(r2), "r"(r3) : "memory");
}

__device__ __forceinline__ uint32_t smem_u32(const void* p) {
    uint32_t a;
    asm("{ .reg .u64 t; cvta.to.shared.u64 t, %1; cvt.u32.u64 %0, t; }"
        : "=r"(a) : "l"(p));
    return a;
}

__device__ __forceinline__ uint32_t packh2(float a, float b) {
    __half2 h = __floats2half2_rn(a, b);
    return *reinterpret_cast<uint32_t*>(&h);
}

// quad-local barrier: 4 warps sharing one m-block (128 threads)
__device__ __forceinline__ void quad_bar(int id) {
    asm volatile("bar.sync %0, %1;" :: "r"(id), "r"(128) : "memory");
}

// ============================ kernel ============================
__global__ __launch_bounds__(NT, 1)
void patch_embed_mma(const float* __restrict__ xyz,
                     const float* __restrict__ centers,
                     const int*   __restrict__ idx_knn,
                     const float* __restrict__ W1,
                     const float* __restrict__ b1,
                     const float* __restrict__ W2,
                     const float* __restrict__ b2,
                     const float* __restrict__ W3,
                     const float* __restrict__ b3,
                     float*       __restrict__ out)
{
    extern __shared__ __align__(16) char smem[];
    __half* sW3h = reinterpret_cast<__half*>(smem + S_W3);
    __half* sH2h = reinterpret_cast<__half*>(smem + S_H2);
    __half* sH1h = reinterpret_cast<__half*>(smem + S_H1);
    __half* sW2h = reinterpret_cast<__half*>(smem + S_W2);
    float*  sB2  = reinterpret_cast<float*>(smem + S_B2);
    float*  sW1v = reinterpret_cast<float*>(smem + S_W1);
    float*  sB1v = reinterpret_cast<float*>(smem + S_B1);

    const int tid  = threadIdx.x;
    const int lane = tid & 31;
    const int wid  = tid >> 5;
    const int gp   = lane >> 2;
    const int tg   = lane & 3;

    // quad pipelines: mtp = m-block (quad id), nq = n quarter within quad.
    const int mtp = wid >> 2;
    const int nq  = wid & 3;
    const int bar = mtp + 1;

    // ---- one-time staging: fp16 weights ------------------------------------
    for (int i = tid; i < 256 * 128; i += NT) {       // W3 [n=256][k=128]
        int n = i >> 7, k = i & 127;
        sW3h[n * PKH + k] = __float2half_rn(W3[i]);
    }
    for (int i = tid; i < 128 * 64; i += NT) {        // W2 [n=128][k=64]
        int n = i >> 6, k = i & 63;
        sW2h[n * PKW + k] = __float2half_rn(W2[i]);
    }
    if (tid < 192) sW1v[tid] = W1[tid];
    if (tid < 64)  sB1v[tid] = b1[tid];
    if (tid < 128) sB2[tid]  = b2[tid];
    __syncthreads();

    // ---- precomputed LDSM base addresses (bytes) ---------------------------
    const uint32_t sH1_b = smem_u32(sH1h);
    const uint32_t sH2_b = smem_u32(sH2h);
    const uint32_t sW3_b = smem_u32(sW3h);
    const uint32_t sW2_b = smem_u32(sW2h);
    // A frags: rows mtp*32 + m*16 + (lane&15), k-half (lane>>4)*8 halfs
    uint32_t a1Addr[2], a2Addr[2];
    #pragma unroll
    for (int m = 0; m < 2; ++m) {
        const int r = mtp*32 + m*16 + (lane & 15);
        const int kh = (lane >> 4) << 3;
        a1Addr[m] = sH1_b + ((r * PKW + kh) << 1);
        a2Addr[m] = sH2_b + ((r * PKH + kh) << 1);
    }
    // B (W3): n = nq*64 + p*16 + (lane&7) + ((lane>>4)<<3); k-half ((lane>>3)&1)*8
    uint32_t b3Addr[4];
    #pragma unroll
    for (int p = 0; p < 4; ++p)
        b3Addr[p] = sW3_b +
            (((nq*64 + p*16 + (lane & 7) + ((lane >> 4) << 3)) * PKH
              + (((lane >> 3) & 1) << 3)) << 1);
    // B (W2): n = nq*32 + p*16 + ...
    uint32_t b2Addr[2];
    #pragma unroll
    for (int p = 0; p < 2; ++p)
        b2Addr[p] = sW2_b +
            (((nq*32 + p*16 + (lane & 7) + ((lane >> 4) << 3)) * PKW
              + (((lane >> 3) & 1) << 3)) << 1);
    // stmatrix base for epi1: instr (m,p) -> base + m*16*PKH*2 + p*32
    const uint32_t stBase = sH2_b +
        ((((mtp*32 + ((lane >> 3) & 1)*8 + (lane & 7)) * PKH)
          + nq*32 + (lane >> 4)*8) << 1);

    // ---- gather state: this thread's fixed row = mtp*32 + lane -------------
    const int row = mtp * 32 + lane;          // quad-local layer-1 row
    const int cb  = nq * 16;                  // 16-channel block

    float px, py, pz;
    {
        const int bm = blockIdx.x * MT + mtp;
        const int ii = __ldg(&idx_knn[bm * KNNk + lane]);
        const float* p = xyz + ((size_t)(bm >> 11) * Np + ii) * 3;
        px = p[0] - __ldg(&centers[bm * 3 + 0]);
        py = p[1] - __ldg(&centers[bm * 3 + 1]);
        pz = p[2] - __ldg(&centers[bm * 3 + 2]);
    }

    for (int g = blockIdx.x; g < NGROUPS; g += GRID) {
        const int bm0 = g * MT;
        const int gn  = (g + GRID < NGROUPS) ? (g + GRID) : g;

        // ---- layer 1: 3->64 relu (fp32 math, fp16 store) -> h1 -------------
        {
            uint32_t pk[8];
            #pragma unroll
            for (int j = 0; j < 8; ++j) {
                const int o0 = cb + 2*j;
                float v0 = sB1v[o0],     v1 = sB1v[o0 + 1];
                v0 = fmaf(sW1v[o0*3 + 0], px, v0);
                v1 = fmaf(sW1v[o0*3 + 3], px, v1);
                v0 = fmaf(sW1v[o0*3 + 1], py, v0);
                v1 = fmaf(sW1v[o0*3 + 4], py, v1);
                v0 = fmaf(sW1v[o0*3 + 2], pz, v0);
                v1 = fmaf(sW1v[o0*3 + 5], pz, v1);
                pk[j] = packh2(fmaxf(v0, 0.f), fmaxf(v1, 0.f));
            }
            uint32_t* h1r = reinterpret_cast<uint32_t*>(sH1h + row * PKW + cb);
            *reinterpret_cast<uint4*>(h1r)     = make_uint4(pk[0], pk[1], pk[2], pk[3]);
            *reinterpret_cast<uint4*>(h1r + 4) = make_uint4(pk[4], pk[5], pk[6], pk[7]);
        }
        // prefetch next group's knn index (overlaps GEMM1)
        const int nbm = gn * MT + mtp;
        const int nii = __ldg(&idx_knn[nbm * KNNk + lane]);

        quad_bar(bar);   // quad's h1 writes visible; prior GEMM2 reads done

        // ---- GEMM1: D1 = h1 * W2^T, 4 k16 steps, 1-step frag lookahead -----
        {
            float acc1[2][4][4];
            #pragma unroll
            for (int m = 0; m < 2; ++m)
                #pragma unroll
                for (int nt = 0; nt < 4; ++nt)
                    #pragma unroll
                    for (int j = 0; j < 4; ++j) acc1[m][nt][j] = 0.f;

            uint32_t a1f[2][2][4], b2f[2][2][4];
            ldsm4(a1f[0][0], a1Addr[0]);
            ldsm4(a1f[0][1], a1Addr[1]);
            ldsm4(b2f[0][0], b2Addr[0]);
            ldsm4(b2f[0][1], b2Addr[1]);

            #pragma unroll
            for (int ks = 0; ks < 4; ++ks) {
                const int cur = ks & 1, nxt = cur ^ 1;
                if (ks < 3) {
                    const uint32_t k4n = (uint32_t)(ks + 1) << 5;
                    ldsm4(a1f[nxt][0], a1Addr[0] + k4n);
                    ldsm4(a1f[nxt][1], a1Addr[1] + k4n);
                    ldsm4(b2f[nxt][0], b2Addr[0] + k4n);
                    ldsm4(b2f[nxt][1], b2Addr[1] + k4n);
                }
                #pragma unroll
                for (int p = 0; p < 2; ++p) {
                    mma16(acc1[0][2*p],     a1f[cur][0], b2f[cur][p][0], b2f[cur][p][1]);
                    mma16(acc1[1][2*p],     a1f[cur][1], b2f[cur][p][0], b2f[cur][p][1]);
                    mma16(acc1[0][2*p + 1], a1f[cur][0], b2f[cur][p][2], b2f[cur][p][3]);
                    mma16(acc1[1][2*p + 1], a1f[cur][1], b2f[cur][p][2], b2f[cur][p][3]);
                }
            }

            // ---- epilogue 1: h2 = fp16(relu(D1 + b2)) via stmatrix ---------
            #pragma unroll
            for (int m = 0; m < 2; ++m)
                #pragma unroll
                for (int p = 0; p < 2; ++p) {
                    uint32_t rr[2][2];
                    #pragma unroll
                    for (int h = 0; h < 2; ++h) {
                        const int nt = 2*p + h;
                        const int c0 = nq*32 + nt*8 + 2*tg;
                        const float bb0 = sB2[c0], bb1 = sB2[c0 + 1];
                        rr[h][0] = packh2(fmaxf(acc1[m][nt][0] + bb0, 0.f),
                                          fmaxf(acc1[m][nt][1] + bb1, 0.f));
                        rr[h][1] = packh2(fmaxf(acc1[m][nt][2] + bb0, 0.f),
                                          fmaxf(acc1[m][nt][3] + bb1, 0.f));
                    }
                    stsm4(stBase + (uint32_t)(m * (16*PKH*2) + p * 32),
                          rr[0][0], rr[0][1], rr[1][0], rr[1][1]);
                }
        }
        // prefetch next group's coords (overlaps GEMM2)
        {
            const float* p = xyz + ((size_t)(nbm >> 11) * Np + nii) * 3;
            px = p[0] - __ldg(&centers[nbm * 3 + 0]);
            py = p[1] - __ldg(&centers[nbm * 3 + 1]);
            pz = p[2] - __ldg(&centers[nbm * 3 + 2]);
        }

        quad_bar(bar);   // quad's h2 writes visible; h1 reads done

        // ---- GEMM2: D2 = h2 * W3^T, 8 k16 steps, 1-step frag lookahead -----
        {
            float acc2[2][8][4];
            #pragma unroll
            for (int m = 0; m < 2; ++m)
                #pragma unroll
                for (int nt = 0; nt < 8; ++nt)
                    #pragma unroll
                    for (int j = 0; j < 4; ++j) acc2[m][nt][j] = 0.f;

            uint32_t a2f[2][2][4];   // [buf][m][4]
            uint32_t b3f[2][4][4];   // [buf][p][4]
            ldsm4(a2f[0][0], a2Addr[0]);
            ldsm4(a2f[0][1], a2Addr[1]);
            #pragma unroll
            for (int p = 0; p < 4; ++p) ldsm4(b3f[0][p], b3Addr[p]);

            #pragma unroll
            for (int ks = 0; ks < 8; ++ks) {
                const int cur = ks & 1, nxt = cur ^ 1;
                if (ks < 7) {
                    const uint32_t k4n = (uint32_t)(ks + 1) << 5;
                    ldsm4(a2f[nxt][0], a2Addr[0] + k4n);
                    ldsm4(a2f[nxt][1], a2Addr[1] + k4n);
                    #pragma unroll
                    for (int p = 0; p < 4; ++p)
                        ldsm4(b3f[nxt][p], b3Addr[p] + k4n);
                }
                #pragma unroll
                for (int p = 0; p < 4; ++p) {
                    mma16(acc2[0][2*p],     a2f[cur][0], b3f[cur][p][0], b3f[cur][p][1]);
                    mma16(acc2[1][2*p],     a2f[cur][1], b3f[cur][p][0], b3f[cur][p][1]);
                    mma16(acc2[0][2*p + 1], a2f[cur][0], b3f[cur][p][2], b3f[cur][p][3]);
                    mma16(acc2[1][2*p + 1], a2f[cur][1], b3f[cur][p][2], b3f[cur][p][3]);
                }
            }

            // ---- max over 32 k-rows of this warp's m-block + b3 + store ----
            const int bm = bm0 + mtp;
            #pragma unroll
            for (int nt = 0; nt < 8; ++nt) {
                float m0 = fmaxf(fmaxf(acc2[0][nt][0], acc2[0][nt][2]),
                                 fmaxf(acc2[1][nt][0], acc2[1][nt][2]));
                float m1 = fmaxf(fmaxf(acc2[0][nt][1], acc2[0][nt][3]),
                                 fmaxf(acc2[1][nt][1], acc2[1][nt][3]));
                #pragma unroll
                for (int s = 4; s < 32; s <<= 1) {
                    m0 = fmaxf(m0, __shfl_xor_sync(0xffffffffu, m0, s));
                    m1 = fmaxf(m1, __shfl_xor_sync(0xffffffffu, m1, s));
                }
                if (lane < 4) {
                    const int c = nq*64 + nt*8 + 2*tg;
                    float2 r2;
                    r2.x = m0 + __ldg(&b3[c]);
                    r2.y = m1 + __ldg(&b3[c + 1]);
                    *reinterpret_cast<float2*>(&out[(size_t)bm * EMBc + c]) = r2;
                }
            }
        }
        // no barrier here: next layer-1 writes h1, whose quad readers are
        // fenced by the first quad_bar of the next iteration.
    }
}

// ============================ launch ============================
extern "C" void kernel_launch(void* const* d_in, const int* in_sizes, int n_in,
                              void* d_out, int out_size)
{
    // metadata order: xyz, centers, idx_knn, W1, b1, W2, b2, W3, b3
    const float* xyz     = (const float*)d_in[0];
    const float* centers = (const float*)d_in[1];
    const int*   idx_knn = (const int*)  d_in[2];
    const float* W1      = (const float*)d_in[3];
    const float* b1      = (const float*)d_in[4];
    const float* W2      = (const float*)d_in[5];
    const float* b2      = (const float*)d_in[6];
    const float* W3      = (const float*)d_in[7];
    const float* b3      = (const float*)d_in[8];
    float* out = (float*)d_out;

    // Idempotent attribute set (capture-safe, no allocation).
    cudaFuncSetAttribute(patch_embed_mma,
                         cudaFuncAttributeMaxDynamicSharedMemorySize,
                         SMEM_BYTES);

    patch_embed_mma<<<GRID, NT, SMEM_BYTES>>>(
        xyz, centers, idx_knn, W1, b1, W2, b2, W3, b3, out);
}

// round 16
// speedup vs baseline: 1.5031x; 1.0444x over previous
#include <cuda_runtime.h>
#include <cuda_fp16.h>
#include <cstdint>

// ============================ problem constants ============================
#define Bn      8
#define Np      16384
#define MCc     2048
#define KNNk    32
#define EMBc    256
#define NC      16384             // total centers (Bn*MCc) = m-blocks
#define GRID    152
#define NQUAD   5                 // independent quad pipelines per CTA
#define NT      (32 * 4 * NQUAD)  // 640 threads, 20 warps
#define STRIDE  (GRID * NQUAD)    // m-block stride per quad stream

// Strides in halfs, padded so ldmatrix/stmatrix 8-row sets are conflict-free
// (row byte-stride mod 128 == 16).
#define PKH  136                  // h2 and W3 k-stride (K=128)
#define PKW  72                   // h1 and W2 k-stride (K=64)

// SMEM byte offsets (16B aligned). h1/h2 hold 32 rows per quad (160 rows).
#define S_W3  0                              // [256][136] half: 69632 B
#define S_H2  69632                          // [160][136] half: 43520 B
#define S_H1  113152                         // [160][72]  half: 23040 B
#define S_W2  136192                         // [128][72]  half: 18432 B
#define S_B2  154624                         // 128 f32
#define S_W1  155136                         // 192 f32
#define S_B1  155904                         // 64 f32
#define SMEM_BYTES 156160

// ============================ PTX helpers ============================
__device__ __forceinline__ void mma16(float* d, const uint32_t* a,
                                      uint32_t b0, uint32_t b1) {
    asm volatile(
        "mma.sync.aligned.m16n8k16.row.col.f32.f16.f16.f32 "
        "{%0,%1,%2,%3}, {%4,%5,%6,%7}, {%8,%9}, {%0,%1,%2,%3};"
        : "+f"(d[0]), "+f"(d[1]), "+f"(d[2]), "+f"(d[3])
        : "r"(a[0]), "r"(a[1]), "r"(a[2]), "r"(a[3]), "r"(b0), "r"(b1));
}

__device__ __forceinline__ void ldsm4(uint32_t* r, uint32_t addr) {
    asm volatile(
        "ldmatrix.sync.aligned.m8n8.x4.shared.b16 {%0,%1,%2,%3}, [%4];"
        : "=r"(r[0]), "=r"(r[1]), "=r"(r[2]), "=r"(r[3]) : "r"(addr));
}

__device__ __forceinline__ void stsm4(uint32_t addr, uint32_t r0, uint32_t r1,
                                      uint32_t r2, uint32_t r3) {
    asm volatile(
        "stmatrix.sync.aligned.m8n8.x4.shared.b16 [%0], {%1,%2,%3,%4};"
        :: "r"(addr), "r"(r0), "r"(r1), "r"(r2), "r"(r3) : "memory");
}

__device__ __forceinline__ uint32_t smem_u32(const void* p) {
    uint32_t a;
    asm("{ .reg .u64 t; cvta.to.shared.u64 t, %1; cvt.u32.u64 %0, t; }"
        : "=r"(a) : "l"(p));
    return a;
}

__device__ __forceinline__ uint32_t packh2(float a, float b) {
    __half2 h = __floats2half2_rn(a, b);
    return *reinterpret_cast<uint32_t*>(&h);
}

// quad-local barrier: 4 warps sharing one m-block stream (128 threads)
__device__ __forceinline__ void quad_bar(int id) {
    asm volatile("bar.sync %0, %1;" :: "r"(id), "r"(128) : "memory");
}

// ============================ kernel ============================
__global__ __launch_bounds__(NT, 1)
void patch_embed_mma(const float* __restrict__ xyz,
                     const float* __restrict__ centers,
                     const int*   __restrict__ idx_knn,
                     const float* __restrict__ W1,
                     const float* __restrict__ b1,
                     const float* __restrict__ W2,
                     const float* __restrict__ b2,
                     const float* __restrict__ W3,
                     const float* __restrict__ b3,
                     float*       __restrict__ out)
{
    extern __shared__ __align__(16) char smem[];
    __half* sW3h = reinterpret_cast<__half*>(smem + S_W3);
    __half* sH2h = reinterpret_cast<__half*>(smem + S_H2);
    __half* sH1h = reinterpret_cast<__half*>(smem + S_H1);
    __half* sW2h = reinterpret_cast<__half*>(smem + S_W2);
    float*  sB2  = reinterpret_cast<float*>(smem + S_B2);
    float*  sW1v = reinterpret_cast<float*>(smem + S_W1);
    float*  sB1v = reinterpret_cast<float*>(smem + S_B1);

    const int tid  = threadIdx.x;
    const int lane = tid & 31;
    const int wid  = tid >> 5;
    const int gp   = lane >> 2;
    const int tg   = lane & 3;

    // 5 independent quad pipelines; quad warps sit on different SMSPs.
    const int mtp = wid >> 2;         // quad id (0..4)
    const int nq  = wid & 3;          // n quarter within quad
    const int bar = mtp + 1;          // named barrier id

    // ---- one-time staging: fp16 weights ------------------------------------
    for (int i = tid; i < 256 * 128; i += NT) {       // W3 [n=256][k=128]
        int n = i >> 7, k = i & 127;
        sW3h[n * PKH + k] = __float2half_rn(W3[i]);
    }
    for (int i = tid; i < 128 * 64; i += NT) {        // W2 [n=128][k=64]
        int n = i >> 6, k = i & 63;
        sW2h[n * PKW + k] = __float2half_rn(W2[i]);
    }
    if (tid < 192) sW1v[tid] = W1[tid];
    if (tid < 64)  sB1v[tid] = b1[tid];
    if (tid < 128) sB2[tid]  = b2[tid];
    __syncthreads();

    // ---- precomputed LDSM base addresses (bytes) ---------------------------
    const uint32_t sH1_b = smem_u32(sH1h);
    const uint32_t sH2_b = smem_u32(sH2h);
    const uint32_t sW3_b = smem_u32(sW3h);
    const uint32_t sW2_b = smem_u32(sW2h);
    // A frags: rows mtp*32 + m*16 + (lane&15), k-half (lane>>4)*8 halfs
    uint32_t a1Addr[2], a2Addr[2];
    #pragma unroll
    for (int m = 0; m < 2; ++m) {
        const int r = mtp*32 + m*16 + (lane & 15);
        const int kh = (lane >> 4) << 3;
        a1Addr[m] = sH1_b + ((r * PKW + kh) << 1);
        a2Addr[m] = sH2_b + ((r * PKH + kh) << 1);
    }
    // B (W3): n = nq*64 + p*16 + (lane&7) + ((lane>>4)<<3); k-half ((lane>>3)&1)*8
    uint32_t b3Addr[4];
    #pragma unroll
    for (int p = 0; p < 4; ++p)
        b3Addr[p] = sW3_b +
            (((nq*64 + p*16 + (lane & 7) + ((lane >> 4) << 3)) * PKH
              + (((lane >> 3) & 1) << 3)) << 1);
    // B (W2): n = nq*32 + p*16 + ...
    uint32_t b2Addr[2];
    #pragma unroll
    for (int p = 0; p < 2; ++p)
        b2Addr[p] = sW2_b +
            (((nq*32 + p*16 + (lane & 7) + ((lane >> 4) << 3)) * PKW
              + (((lane >> 3) & 1) << 3)) << 1);
    // stmatrix base for epi1: instr (m,p) -> base + m*16*PKH*2 + p*32
    const uint32_t stBase = sH2_b +
        ((((mtp*32 + ((lane >> 3) & 1)*8 + (lane & 7)) * PKH)
          + nq*32 + (lane >> 4)*8) << 1);

    // ---- layer-1 row for this thread ---------------------------------------
    const int row = mtp * 32 + lane;          // quad-local h1 row
    const int cb  = nq * 16;                  // 16-channel block

    float px, py, pz;
    {
        const int bm = blockIdx.x * NQUAD + mtp;
        if (bm < NC) {
            const int ii = __ldg(&idx_knn[bm * KNNk + lane]);
            const float* p = xyz + ((size_t)(bm >> 11) * Np + ii) * 3;
            px = p[0] - __ldg(&centers[bm * 3 + 0]);
            py = p[1] - __ldg(&centers[bm * 3 + 1]);
            pz = p[2] - __ldg(&centers[bm * 3 + 2]);
        } else { px = py = pz = 0.f; }
    }

    for (int bm = blockIdx.x * NQUAD + mtp; bm < NC; bm += STRIDE) {
        const int nbm0 = bm + STRIDE;
        const int nbm  = (nbm0 < NC) ? nbm0 : bm;

        // ---- layer 1: 3->64 relu (fp32 math, fp16 store) -> h1 -------------
        {
            uint32_t pk[8];
            #pragma unroll
            for (int j = 0; j < 8; ++j) {
                const int o0 = cb + 2*j;
                float v0 = sB1v[o0],     v1 = sB1v[o0 + 1];
                v0 = fmaf(sW1v[o0*3 + 0], px, v0);
                v1 = fmaf(sW1v[o0*3 + 3], px, v1);
                v0 = fmaf(sW1v[o0*3 + 1], py, v0);
                v1 = fmaf(sW1v[o0*3 + 4], py, v1);
                v0 = fmaf(sW1v[o0*3 + 2], pz, v0);
                v1 = fmaf(sW1v[o0*3 + 5], pz, v1);
                pk[j] = packh2(fmaxf(v0, 0.f), fmaxf(v1, 0.f));
            }
            uint32_t* h1r = reinterpret_cast<uint32_t*>(sH1h + row * PKW + cb);
            *reinterpret_cast<uint4*>(h1r)     = make_uint4(pk[0], pk[1], pk[2], pk[3]);
            *reinterpret_cast<uint4*>(h1r + 4) = make_uint4(pk[4], pk[5], pk[6], pk[7]);
        }
        // prefetch next m-block's knn index (overlaps GEMM1)
        const int nii = __ldg(&idx_knn[nbm * KNNk + lane]);

        quad_bar(bar);   // quad's h1 writes visible; prior GEMM2 reads done

        // ---- GEMM1: D1[32 x 128] = h1 * W2^T  (4 k16 steps) ----------------
        {
            float acc1[2][4][4];
            #pragma unroll
            for (int m = 0; m < 2; ++m)
                #pragma unroll
                for (int nt = 0; nt < 4; ++nt)
                    #pragma unroll
                    for (int j = 0; j < 4; ++j) acc1[m][nt][j] = 0.f;

            #pragma unroll
            for (int ks = 0; ks < 4; ++ks) {
                const uint32_t k4 = (uint32_t)ks << 5;   // 16 halfs = 32 B
                uint32_t a0[4], a1[4];
                ldsm4(a0, a1Addr[0] + k4);
                ldsm4(a1, a1Addr[1] + k4);
                #pragma unroll
                for (int p = 0; p < 2; ++p) {
                    uint32_t bf[4];
                    ldsm4(bf, b2Addr[p] + k4);
                    mma16(acc1[0][2*p],     a0, bf[0], bf[1]);
                    mma16(acc1[1][2*p],     a1, bf[0], bf[1]);
                    mma16(acc1[0][2*p + 1], a0, bf[2], bf[3]);
                    mma16(acc1[1][2*p + 1], a1, bf[2], bf[3]);
                }
            }

            // ---- epilogue 1: h2 = fp16(relu(D1 + b2)) via stmatrix ---------
            #pragma unroll
            for (int m = 0; m < 2; ++m)
                #pragma unroll
                for (int p = 0; p < 2; ++p) {
                    uint32_t rr[2][2];
                    #pragma unroll
                    for (int h = 0; h < 2; ++h) {
                        const int nt = 2*p + h;
                        const int c0 = nq*32 + nt*8 + 2*tg;
                        const float bb0 = sB2[c0], bb1 = sB2[c0 + 1];
                        rr[h][0] = packh2(fmaxf(acc1[m][nt][0] + bb0, 0.f),
                                          fmaxf(acc1[m][nt][1] + bb1, 0.f));
                        rr[h][1] = packh2(fmaxf(acc1[m][nt][2] + bb0, 0.f),
                                          fmaxf(acc1[m][nt][3] + bb1, 0.f));
                    }
                    stsm4(stBase + (uint32_t)(m * (16*PKH*2) + p * 32),
                          rr[0][0], rr[0][1], rr[1][0], rr[1][1]);
                }
        }
        // prefetch next m-block's coords (overlaps GEMM2)
        {
            const float* p = xyz + ((size_t)(nbm >> 11) * Np + nii) * 3;
            px = p[0] - __ldg(&centers[nbm * 3 + 0]);
            py = p[1] - __ldg(&centers[nbm * 3 + 1]);
            pz = p[2] - __ldg(&centers[nbm * 3 + 2]);
        }

        quad_bar(bar);   // quad's h2 writes visible; h1 reads done

        // ---- GEMM2 in two n-halves (acc 32 regs each): D2 = h2 * W3^T ------
        #pragma unroll
        for (int h = 0; h < 2; ++h) {
            float acc2[2][4][4];
            #pragma unroll
            for (int m = 0; m < 2; ++m)
                #pragma unroll
                for (int nt = 0; nt < 4; ++nt)
                    #pragma unroll
                    for (int j = 0; j < 4; ++j) acc2[m][nt][j] = 0.f;

            #pragma unroll
            for (int ks = 0; ks < 8; ++ks) {
                const uint32_t k4 = (uint32_t)ks << 5;
                uint32_t a0[4], a1[4];
                ldsm4(a0, a2Addr[0] + k4);
                ldsm4(a1, a2Addr[1] + k4);
                #pragma unroll
                for (int pp = 0; pp < 2; ++pp) {
                    uint32_t bf[4];
                    ldsm4(bf, b3Addr[2*h + pp] + k4);
                    mma16(acc2[0][2*pp],     a0, bf[0], bf[1]);
                    mma16(acc2[1][2*pp],     a1, bf[0], bf[1]);
                    mma16(acc2[0][2*pp + 1], a0, bf[2], bf[3]);
                    mma16(acc2[1][2*pp + 1], a1, bf[2], bf[3]);
                }
            }

            // ---- max over the 32 k-rows + b3 + store (this n-half) ---------
            #pragma unroll
            for (int nt = 0; nt < 4; ++nt) {
                float m0 = fmaxf(fmaxf(acc2[0][nt][0], acc2[0][nt][2]),
                                 fmaxf(acc2[1][nt][0], acc2[1][nt][2]));
                float m1 = fmaxf(fmaxf(acc2[0][nt][1], acc2[0][nt][3]),
                                 fmaxf(acc2[1][nt][1], acc2[1][nt][3]));
                #pragma unroll
                for (int s = 4; s < 32; s <<= 1) {
                    m0 = fmaxf(m0, __shfl_xor_sync(0xffffffffu, m0, s));
                    m1 = fmaxf(m1, __shfl_xor_sync(0xffffffffu, m1, s));
                }
                if (lane < 4) {
                    const int c = nq*64 + h*32 + nt*8 + 2*tg;
                    float2 r2;
                    r2.x = m0 + __ldg(&b3[c]);
                    r2.y = m1 + __ldg(&b3[c + 1]);
                    *reinterpret_cast<float2*>(&out[(size_t)bm * EMBc + c]) = r2;
                }
            }
        }
        // no barrier here: next layer-1 writes h1, whose quad readers are
        // fenced by the first quad_bar of the next iteration.
    }
}

// ============================ launch ============================
extern "C" void kernel_launch(void* const* d_in, const int* in_sizes, int n_in,
                              void* d_out, int out_size)
{
    // metadata order: xyz, centers, idx_knn, W1, b1, W2, b2, W3, b3
    const float* xyz     = (const float*)d_in[0];
    const float* centers = (const float*)d_in[1];
    const int*   idx_knn = (const int*)  d_in[2];
    const float* W1      = (const float*)d_in[3];
    const float* b1      = (const float*)d_in[4];
    const float* W2      = (const float*)d_in[5];
    const float* b2      = (const float*)d_in[6];
    const float* W3      = (const float*)d_in[7];
    const float* b3      = (const float*)d_in[8];
    float* out = (float*)d_out;

    // Idempotent attribute set (capture-safe, no allocation).
    cudaFuncSetAttribute(patch_embed_mma,
                         cudaFuncAttributeMaxDynamicSharedMemorySize,
                         SMEM_BYTES);

    patch_embed_mma<<<GRID, NT, SMEM_BYTES>>>(
        xyz, centers, idx_knn, W1, b1, W2, b2, W3, b3, out);
}